// round 13
// baseline (speedup 1.0000x reference)
#include <cuda_runtime.h>
#include <math_constants.h>

#define BATCH 64

// scratch
__device__ float g_conv1[BATCH * 16384];
__device__ float g_out2[BATCH * 4096];
__device__ float g_out3[BATCH * 4096];
__device__ float g_h[BATCH * 256];
__device__ float g_logits[BATCH * 1024];
__device__ float g_wpack[1371136];
__device__ float2 g_part1[BATCH * 64];
__device__ float2 g_part2[BATCH * 16];
__device__ float2 g_part3[BATCH * 16];

// packed-weight offsets (floats). Layout: [k-group][pos][4] so adjacent
// positions are 16B apart -> warp LDG.128 touches 4 lines, not 32.
#define OFF_W1 0          // 13 groups x 16384 x 4 = 851968
#define OFF_W2 851968     // 7 x 4096 x 4 = 114688
#define OFF_W3 966656     // 7 x 4096 x 4 = 114688
#define OFF_W4 1081344    // 3 x 1024 x 4 = 12288
#define OFF_W5 1093632    // 3 x 1024 x 4 = 12288
#define OFF_W6 1105920    // 3 x 256 x 4 = 3072
#define OFF_FCT 1108992   // fcwT[256][1024] = 262144

// ---------------------------------------------------------------------------
__global__ void repack_kernel(const float* __restrict__ w1, const float* __restrict__ w2,
                              const float* __restrict__ w3, const float* __restrict__ w4,
                              const float* __restrict__ w5, const float* __restrict__ w6,
                              const float* __restrict__ fcw,
                              float* __restrict__ wp) {
    int tid = blockIdx.x * blockDim.x + threadIdx.x;
    int nt = gridDim.x * blockDim.x;
    for (int i = tid; i < 16384 * 49; i += nt) {
        int p = i / 49, k = i - p * 49;
        wp[OFF_W1 + ((k >> 2) * 16384 + p) * 4 + (k & 3)] = w1[i];
    }
    for (int i = tid; i < 4096 * 25; i += nt) {
        int p = i / 25, k = i - p * 25;
        wp[OFF_W2 + ((k >> 2) * 4096 + p) * 4 + (k & 3)] = w2[i];
    }
    for (int i = tid; i < 4096 * 25; i += nt) {
        int p = i / 25, k = i - p * 25;
        wp[OFF_W3 + ((k >> 2) * 4096 + p) * 4 + (k & 3)] = w3[i];
    }
    for (int i = tid; i < 1024 * 9; i += nt) {
        int p = i / 9, k = i - p * 9;
        wp[OFF_W4 + ((k >> 2) * 1024 + p) * 4 + (k & 3)] = w4[i];
    }
    for (int i = tid; i < 1024 * 9; i += nt) {
        int p = i / 9, k = i - p * 9;
        wp[OFF_W5 + ((k >> 2) * 1024 + p) * 4 + (k & 3)] = w5[i];
    }
    for (int i = tid; i < 256 * 9; i += nt) {
        int p = i / 9, k = i - p * 9;
        wp[OFF_W6 + ((k >> 2) * 256 + p) * 4 + (k & 3)] = w6[i];
    }
    // fcwT[k][o] = fcw[o][k]; i = k*1024 + o -> coalesced writes
    for (int i = tid; i < 262144; i += nt) {
        int o = i & 1023, k = i >> 10;
        wp[OFF_FCT + i] = fcw[o * 256 + k];
    }
}

// ---------------------------------------------------------------------------
// Conv1: 128x128, K=7, pad=3, + ReLU. Block = 8x32 tile x 8-batch group.
// Grid (64,8), 256 threads.
// ---------------------------------------------------------------------------
__global__ void __launch_bounds__(256) conv1_kernel(const float* __restrict__ x,
                                                    const float* __restrict__ wp,
                                                    const float* __restrict__ b1,
                                                    float* __restrict__ out,
                                                    float2* __restrict__ part1) {
    __shared__ float sm[8][14][40];
    __shared__ float rs[8][8], rq[8][8];
    const int tile = blockIdx.x;
    const int bg = blockIdx.y;
    const int tx = tile & 3, ty = tile >> 2;
    const int tj0 = tx * 32, ti0 = ty * 8;
    const int tid = threadIdx.x;

    // weights first: latency overlaps input staging
    const int ti = tid >> 5, tj = tid & 31;
    const int p = (ti0 + ti) * 128 + (tj0 + tj);
    float4 wreg[13];
    const float4* wv = (const float4*)(wp + OFF_W1);
#pragma unroll
    for (int t = 0; t < 13; ++t) wreg[t] = __ldg(wv + t * 16384 + p);
    const float* wf = (const float*)wreg;
    const float bias = __ldg(b1 + p);

    for (int e = tid; e < 1120; e += 256) {
        int bb = e / 140;
        int rem = e - bb * 140;
        int r = rem / 10, k = rem - r * 10;
        int gi = ti0 - 3 + r;
        int c = tj0 - 4 + 4 * k;
        float4 v = make_float4(0.f, 0.f, 0.f, 0.f);
        if ((unsigned)gi < 128u && (unsigned)c <= 124u)
            v = *(const float4*)(x + (bg * 8 + bb) * 16384 + gi * 128 + c);
        *(float4*)(&sm[bb][r][4 * k]) = v;
    }
    __syncthreads();

    float r8[8];
#pragma unroll
    for (int bb = 0; bb < 8; bb += 4) {
        float a0 = bias, a1 = bias, a2 = bias, a3 = bias;
#pragma unroll
        for (int u = 0; u < 7; ++u)
#pragma unroll
            for (int v = 0; v < 7; ++v) {
                float wvv = wf[u * 7 + v];
                a0 = fmaf(sm[bb + 0][ti + u][tj + v + 1], wvv, a0);
                a1 = fmaf(sm[bb + 1][ti + u][tj + v + 1], wvv, a1);
                a2 = fmaf(sm[bb + 2][ti + u][tj + v + 1], wvv, a2);
                a3 = fmaf(sm[bb + 3][ti + u][tj + v + 1], wvv, a3);
            }
        r8[bb + 0] = fmaxf(a0, 0.0f);
        r8[bb + 1] = fmaxf(a1, 0.0f);
        r8[bb + 2] = fmaxf(a2, 0.0f);
        r8[bb + 3] = fmaxf(a3, 0.0f);
    }
#pragma unroll
    for (int bb = 0; bb < 8; ++bb)
        out[(bg * 8 + bb) * 16384 + p] = r8[bb];

    const int wid = tid >> 5, lid = tid & 31;
#pragma unroll
    for (int s = 0; s < 8; ++s) {
        float v = r8[s], q = v * v;
#pragma unroll
        for (int o = 16; o; o >>= 1) {
            v += __shfl_down_sync(0xFFFFFFFFu, v, o);
            q += __shfl_down_sync(0xFFFFFFFFu, q, o);
        }
        if (lid == 0) { rs[wid][s] = v; rq[wid][s] = q; }
    }
    __syncthreads();
    if (tid < 8) {
        float s_ = 0.0f, q_ = 0.0f;
#pragma unroll
        for (int w = 0; w < 8; ++w) { s_ += rs[w][tid]; q_ += rq[w][tid]; }
        part1[(bg * 8 + tid) * 64 + tile] = make_float2(s_, q_);
    }
}

// ---------------------------------------------------------------------------
// conv2k: LN1(+g1,be1) + 2x2 pool on the fly (g/be read direct, no staging),
// then conv2 (64x64, K=5). Grid (16 tiles, 16 groups of 4), 256 threads.
// Weights hoisted to kernel top.
// ---------------------------------------------------------------------------
__global__ void __launch_bounds__(256) conv2k_kernel(const float* __restrict__ c1,
                                                     const float2* __restrict__ part1,
                                                     const float* __restrict__ g1,
                                                     const float* __restrict__ be1,
                                                     const float* __restrict__ wp,
                                                     const float* __restrict__ b2,
                                                     float* __restrict__ out2,
                                                     float2* __restrict__ part2) {
    __shared__ float P[4][20][24];
    __shared__ float2 stats[4];
    __shared__ float rs[8][4], rq[8][4];
    const int tile = blockIdx.x, bg = blockIdx.y;
    const int oj0 = (tile & 3) * 16, oi0 = (tile >> 2) * 16;
    const int tid = threadIdx.x, wid = tid >> 5, lid = tid & 31;

    // weights + bias first (no deps; overlaps stats + staging)
    const int ti = tid >> 4, tj = tid & 15;
    const int p = (oi0 + ti) * 64 + (oj0 + tj);
    float4 wq[7];
    const float4* wvp = (const float4*)(wp + OFF_W2);
#pragma unroll
    for (int t = 0; t < 7; ++t) wq[t] = __ldg(wvp + t * 4096 + p);
    const float* wf = (const float*)wq;
    const float bias = __ldg(b2 + p);

    // LN1 stats: warps 0-3 reduce sample bg*4+wid over 64 tile-partials
    if (wid < 4) {
        int s = bg * 4 + wid;
        float2 a = __ldg(&part1[s * 64 + lid]);
        float2 b = __ldg(&part1[s * 64 + 32 + lid]);
        float sum = a.x + b.x, ssq = a.y + b.y;
#pragma unroll
        for (int o = 16; o; o >>= 1) {
            sum += __shfl_down_sync(0xFFFFFFFFu, sum, o);
            ssq += __shfl_down_sync(0xFFFFFFFFu, ssq, o);
        }
        if (lid == 0) {
            float mu = sum * (1.0f / 16384.0f);
            float var = ssq * (1.0f / 16384.0f) - mu * mu;
            stats[wid] = make_float2(mu, rsqrtf(var + 1e-5f));
        }
    }
    __syncthreads();

    // build pooled-normalized P[4][20][20] (cols padded to 24); g/be direct
    for (int e = tid; e < 800; e += 256) {
        int sIdx = e / 200;
        int rem = e - sIdx * 200;
        int pr = rem / 10, g = rem - pr * 10;
        int pi = oi0 - 2 + pr;
        int pjA = oj0 - 2 + 2 * g;
        float pv0 = 0.0f, pv1 = 0.0f;
        if ((unsigned)pi < 64u && (unsigned)pjA < 63u) {
            float mu = stats[sIdx].x, rstd = stats[sIdx].y;
            int r0 = 2 * pi, c0 = 2 * pjA;
            const float* base = c1 + (bg * 4 + sIdx) * 16384;
            float4 x0 = *(const float4*)(base + r0 * 128 + c0);
            float4 x1 = *(const float4*)(base + (r0 + 1) * 128 + c0);
            float4 G0 = *(const float4*)(g1 + r0 * 128 + c0);
            float4 G1 = *(const float4*)(g1 + (r0 + 1) * 128 + c0);
            float4 B0 = *(const float4*)(be1 + r0 * 128 + c0);
            float4 B1 = *(const float4*)(be1 + (r0 + 1) * 128 + c0);
            float n00 = (x0.x - mu) * rstd * G0.x + B0.x;
            float n01 = (x0.y - mu) * rstd * G0.y + B0.y;
            float n10 = (x1.x - mu) * rstd * G1.x + B1.x;
            float n11 = (x1.y - mu) * rstd * G1.y + B1.y;
            pv0 = fmaxf(fmaxf(n00, n01), fmaxf(n10, n11));
            float m02 = (x0.z - mu) * rstd * G0.z + B0.z;
            float m03 = (x0.w - mu) * rstd * G0.w + B0.w;
            float m12 = (x1.z - mu) * rstd * G1.z + B1.z;
            float m13 = (x1.w - mu) * rstd * G1.w + B1.w;
            pv1 = fmaxf(fmaxf(m02, m03), fmaxf(m12, m13));
        }
        P[sIdx][pr][2 * g] = pv0;
        P[sIdx][pr][2 * g + 1] = pv1;
    }
    __syncthreads();

    float outv[4];
#pragma unroll
    for (int s = 0; s < 4; ++s) {
        float acc = bias;
#pragma unroll
        for (int u = 0; u < 5; ++u)
#pragma unroll
            for (int v = 0; v < 5; ++v)
                acc = fmaf(P[s][ti + u][tj + v], wf[u * 5 + v], acc);
        outv[s] = fmaxf(acc, 0.0f);
        out2[(bg * 4 + s) * 4096 + p] = outv[s];
    }
#pragma unroll
    for (int s = 0; s < 4; ++s) {
        float v = outv[s], q = v * v;
#pragma unroll
        for (int o = 16; o; o >>= 1) {
            v += __shfl_down_sync(0xFFFFFFFFu, v, o);
            q += __shfl_down_sync(0xFFFFFFFFu, q, o);
        }
        if (lid == 0) { rs[wid][s] = v; rq[wid][s] = q; }
    }
    __syncthreads();
    if (tid < 4) {
        float s_ = 0.0f, q_ = 0.0f;
#pragma unroll
        for (int w = 0; w < 8; ++w) { s_ += rs[w][tid]; q_ += rq[w][tid]; }
        part2[(bg * 4 + tid) * 16 + tile] = make_float2(s_, q_);
    }
}

// ---------------------------------------------------------------------------
// conv3k: LN2(+g2,be2) applied during staging (g/be direct), conv3 (64x64,
// K=5). Grid (16, 16 groups of 4), 256 threads. Weights hoisted to top.
// ---------------------------------------------------------------------------
__global__ void __launch_bounds__(256) conv3k_kernel(const float* __restrict__ in2,
                                                     const float2* __restrict__ part2,
                                                     const float* __restrict__ g2,
                                                     const float* __restrict__ be2,
                                                     const float* __restrict__ wp,
                                                     const float* __restrict__ b3,
                                                     float* __restrict__ out3,
                                                     float2* __restrict__ part3) {
    __shared__ float N[4][20][24];
    __shared__ float2 stats[4];
    __shared__ float rs[8][4], rq[8][4];
    const int tile = blockIdx.x, bg = blockIdx.y;
    const int oj0 = (tile & 3) * 16, oi0 = (tile >> 2) * 16;
    const int tid = threadIdx.x, wid = tid >> 5, lid = tid & 31;

    // weights + bias first
    const int ti = tid >> 4, tj = tid & 15;
    const int p = (oi0 + ti) * 64 + (oj0 + tj);
    float4 wq[7];
    const float4* wvp = (const float4*)(wp + OFF_W3);
#pragma unroll
    for (int t = 0; t < 7; ++t) wq[t] = __ldg(wvp + t * 4096 + p);
    const float* wf = (const float*)wq;
    const float bias = __ldg(b3 + p);

    if (wid < 4) {
        int s = bg * 4 + wid;
        float2 a = (lid < 16) ? __ldg(&part2[s * 16 + lid]) : make_float2(0.f, 0.f);
        float sum = a.x, ssq = a.y;
#pragma unroll
        for (int o = 16; o; o >>= 1) {
            sum += __shfl_down_sync(0xFFFFFFFFu, sum, o);
            ssq += __shfl_down_sync(0xFFFFFFFFu, ssq, o);
        }
        if (lid == 0) {
            float mu = sum * (1.0f / 4096.0f);
            float var = ssq * (1.0f / 4096.0f) - mu * mu;
            stats[wid] = make_float2(mu, rsqrtf(var + 1e-5f));
        }
    }
    __syncthreads();

    for (int e = tid; e < 480; e += 256) {
        int sIdx = e / 120;
        int rem = e - sIdx * 120;
        int q = rem / 6, k = rem - q * 6;
        int ri = oi0 - 2 + q;
        int c = oj0 - 4 + 4 * k;
        float4 nv = make_float4(0.f, 0.f, 0.f, 0.f);
        if ((unsigned)ri < 64u && (unsigned)c <= 60u) {
            float mu = stats[sIdx].x, rstd = stats[sIdx].y;
            float4 xv = *(const float4*)(in2 + (bg * 4 + sIdx) * 4096 + ri * 64 + c);
            float4 Gv = *(const float4*)(g2 + ri * 64 + c);
            float4 Bv = *(const float4*)(be2 + ri * 64 + c);
            nv.x = (xv.x - mu) * rstd * Gv.x + Bv.x;
            nv.y = (xv.y - mu) * rstd * Gv.y + Bv.y;
            nv.z = (xv.z - mu) * rstd * Gv.z + Bv.z;
            nv.w = (xv.w - mu) * rstd * Gv.w + Bv.w;
        }
        *(float4*)(&N[sIdx][q][4 * k]) = nv;
    }
    __syncthreads();

    float outv[4];
#pragma unroll
    for (int s = 0; s < 4; ++s) {
        float acc = bias;
#pragma unroll
        for (int u = 0; u < 5; ++u)
#pragma unroll
            for (int v = 0; v < 5; ++v)
                acc = fmaf(N[s][ti + u][tj + v + 2], wf[u * 5 + v], acc);
        outv[s] = fmaxf(acc, 0.0f);
        out3[(bg * 4 + s) * 4096 + p] = outv[s];
    }
#pragma unroll
    for (int s = 0; s < 4; ++s) {
        float v = outv[s], q = v * v;
#pragma unroll
        for (int o = 16; o; o >>= 1) {
            v += __shfl_down_sync(0xFFFFFFFFu, v, o);
            q += __shfl_down_sync(0xFFFFFFFFu, q, o);
        }
        if (lid == 0) { rs[wid][s] = v; rq[wid][s] = q; }
    }
    __syncthreads();
    if (tid < 4) {
        float s_ = 0.0f, q_ = 0.0f;
#pragma unroll
        for (int w = 0; w < 8; ++w) { s_ += rs[w][tid]; q_ += rq[w][tid]; }
        part3[(bg * 4 + tid) * 16 + tile] = make_float2(s_, q_);
    }
}

// ---------------------------------------------------------------------------
__device__ __forceinline__ float2 bstats(float s, float ss) {
    __shared__ float r0[32], r1[32];
    int tid = threadIdx.x, wid = tid >> 5, lid = tid & 31;
#pragma unroll
    for (int o = 16; o; o >>= 1) {
        s += __shfl_down_sync(0xFFFFFFFFu, s, o);
        ss += __shfl_down_sync(0xFFFFFFFFu, ss, o);
    }
    if (lid == 0) { r0[wid] = s; r1[wid] = ss; }
    __syncthreads();
    if (wid == 0) {
        s = r0[lid];
        ss = r1[lid];
#pragma unroll
        for (int o = 16; o; o >>= 1) {
            s += __shfl_down_sync(0xFFFFFFFFu, s, o);
            ss += __shfl_down_sync(0xFFFFFFFFu, ss, o);
        }
        if (lid == 0) { r0[0] = s; r1[0] = ss; }
    }
    __syncthreads();
    float2 res = make_float2(r0[0], r1[0]);
    __syncthreads();
    return res;
}

// ---------------------------------------------------------------------------
// tail: LN3+pool -> conv4 -> LN4 -> conv5 -> LN5+pool -> conv6 -> LN6 -> h.
// Block per sample (grid=64, 1024 threads).
// ---------------------------------------------------------------------------
#define MT 1024
__global__ void __launch_bounds__(MT) tail_kernel(
    const float* __restrict__ in3, const float2* __restrict__ part3,
    const float* __restrict__ g3, const float* __restrict__ be3,
    const float* __restrict__ wp,
    const float* __restrict__ b4, const float* __restrict__ g4, const float* __restrict__ be4,
    const float* __restrict__ b5, const float* __restrict__ g5, const float* __restrict__ be5,
    const float* __restrict__ b6, const float* __restrict__ g6, const float* __restrict__ be6,
    float* __restrict__ hout) {
    __shared__ float SA[1156], SB[1156];
    __shared__ float2 st3;
    const int tid = threadIdx.x;
    const int b = blockIdx.x;

    for (int e = tid; e < 2312; e += MT) (e < 1156 ? SA : SB - 1156)[e] = 0.0f;
    if (tid < 32) {
        float2 a = (tid < 16) ? __ldg(&part3[b * 16 + tid]) : make_float2(0.f, 0.f);
        float sum = a.x, ssq = a.y;
#pragma unroll
        for (int o = 16; o; o >>= 1) {
            sum += __shfl_down_sync(0xFFFFFFFFu, sum, o);
            ssq += __shfl_down_sync(0xFFFFFFFFu, ssq, o);
        }
        if (tid == 0) {
            float mu = sum * (1.0f / 4096.0f);
            float var = ssq * (1.0f / 4096.0f) - mu * mu;
            st3 = make_float2(mu, rsqrtf(var + 1e-5f));
        }
    }
    __syncthreads();

    {
        float mu = st3.x, rstd = st3.y;
        const float* base = in3 + b * 4096;
        for (int e = tid; e < 512; e += MT) {
            int pr = e >> 4, g = e & 15;
            int r0 = 2 * pr, c = 4 * g;
            float4 x0 = *(const float4*)(base + r0 * 64 + c);
            float4 x1 = *(const float4*)(base + (r0 + 1) * 64 + c);
            float4 G0 = *(const float4*)(g3 + r0 * 64 + c);
            float4 G1 = *(const float4*)(g3 + (r0 + 1) * 64 + c);
            float4 B0 = *(const float4*)(be3 + r0 * 64 + c);
            float4 B1 = *(const float4*)(be3 + (r0 + 1) * 64 + c);
            float n00 = (x0.x - mu) * rstd * G0.x + B0.x;
            float n01 = (x0.y - mu) * rstd * G0.y + B0.y;
            float n10 = (x1.x - mu) * rstd * G1.x + B1.x;
            float n11 = (x1.y - mu) * rstd * G1.y + B1.y;
            SB[(pr + 1) * 34 + 2 * g + 1] = fmaxf(fmaxf(n00, n01), fmaxf(n10, n11));
            float m02 = (x0.z - mu) * rstd * G0.z + B0.z;
            float m03 = (x0.w - mu) * rstd * G0.w + B0.w;
            float m12 = (x1.z - mu) * rstd * G1.z + B1.z;
            float m13 = (x1.w - mu) * rstd * G1.w + B1.w;
            SB[(pr + 1) * 34 + 2 * g + 2] = fmaxf(fmaxf(m02, m03), fmaxf(m12, m13));
        }
    }
    __syncthreads();

    // conv4
    float s = 0.0f, ss = 0.0f;
    for (int e = tid; e < 1156; e += MT) {
        int i34 = e / 34, j34 = e - i34 * 34;
        if (i34 == 0 || i34 == 33 || j34 == 0 || j34 == 33) { SA[e] = 0.0f; continue; }
        int io = i34 - 1, jo = j34 - 1;
        int p = io * 32 + jo;
        float4 wq[3];
        const float4* wv4 = (const float4*)(wp + OFF_W4);
#pragma unroll
        for (int t = 0; t < 3; ++t) wq[t] = __ldg(wv4 + t * 1024 + p);
        const float* wf = (const float*)wq;
        const float* src = SB + io * 34 + jo;
        float acc = __ldg(b4 + p);
#pragma unroll
        for (int u = 0; u < 3; ++u)
#pragma unroll
            for (int v = 0; v < 3; ++v)
                acc = fmaf(src[u * 34 + v], wf[u * 3 + v], acc);
        acc = fmaxf(acc, 0.0f);
        SA[e] = acc;
        s += acc; ss += acc * acc;
    }
    float2 st = bstats(s, ss);
    float mu = st.x * (1.0f / 1024.0f);
    float rstd = rsqrtf(st.y * (1.0f / 1024.0f) - mu * mu + 1e-5f);
    for (int p = tid; p < 1024; p += MT) {
        int idx = ((p >> 5) + 1) * 34 + (p & 31) + 1;
        SA[idx] = (SA[idx] - mu) * rstd * __ldg(g4 + p) + __ldg(be4 + p);
    }
    __syncthreads();

    // conv5
    s = ss = 0.0f;
    for (int p = tid; p < 1024; p += MT) {
        int i = p >> 5, j = p & 31;
        float4 wq[3];
        const float4* wv5 = (const float4*)(wp + OFF_W5);
#pragma unroll
        for (int t = 0; t < 3; ++t) wq[t] = __ldg(wv5 + t * 1024 + p);
        const float* wf = (const float*)wq;
        const float* src = SA + i * 34 + j;
        float acc = __ldg(b5 + p);
#pragma unroll
        for (int u = 0; u < 3; ++u)
#pragma unroll
            for (int v = 0; v < 3; ++v)
                acc = fmaf(src[u * 34 + v], wf[u * 3 + v], acc);
        acc = fmaxf(acc, 0.0f);
        SB[(i + 1) * 34 + j + 1] = acc;
        s += acc; ss += acc * acc;
    }
    st = bstats(s, ss);
    mu = st.x * (1.0f / 1024.0f);
    rstd = rsqrtf(st.y * (1.0f / 1024.0f) - mu * mu + 1e-5f);
    for (int e = tid; e < 324; e += MT) {
        int i18 = e / 18, j18 = e - i18 * 18;
        if (i18 == 0 || i18 == 17 || j18 == 0 || j18 == 17) { SA[e] = 0.0f; continue; }
        int io = i18 - 1, jo = j18 - 1;
        float m = -CUDART_INF_F;
#pragma unroll
        for (int di = 0; di < 2; ++di)
#pragma unroll
            for (int dj = 0; dj < 2; ++dj) {
                int gi = 2 * io + di, gj = 2 * jo + dj;
                int q = gi * 32 + gj;
                float v = (SB[(gi + 1) * 34 + gj + 1] - mu) * rstd * __ldg(g5 + q) + __ldg(be5 + q);
                m = fmaxf(m, v);
            }
        SA[e] = m;
    }
    __syncthreads();

    // conv6
    s = ss = 0.0f;
    for (int p = tid; p < 256; p += MT) {
        int i = p >> 4, j = p & 15;
        float4 wq[3];
        const float4* wv6 = (const float4*)(wp + OFF_W6);
#pragma unroll
        for (int t = 0; t < 3; ++t) wq[t] = __ldg(wv6 + t * 256 + p);
        const float* wf = (const float*)wq;
        const float* src = SA + i * 18 + j;
        float acc = __ldg(b6 + p);
#pragma unroll
        for (int u = 0; u < 3; ++u)
#pragma unroll
            for (int v = 0; v < 3; ++v)
                acc = fmaf(src[u * 18 + v], wf[u * 3 + v], acc);
        acc = fmaxf(acc, 0.0f);
        SB[p] = acc;
        s += acc; ss += acc * acc;
    }
    st = bstats(s, ss);
    mu = st.x * (1.0f / 256.0f);
    rstd = rsqrtf(st.y * (1.0f / 256.0f) - mu * mu + 1e-5f);
    for (int p = tid; p < 256; p += MT)
        hout[b * 256 + p] = (SB[p] - mu) * rstd * __ldg(g6 + p) + __ldg(be6 + p);
}

// ---------------------------------------------------------------------------
// FC, shuffle-free with transposed weights: grid (4 col-tiles, 64 samples),
// 256 threads, thread-per-output. fcwT[k][o]: warp load = 1 cache line.
// ---------------------------------------------------------------------------
__global__ void __launch_bounds__(256) fc_kernel(const float* __restrict__ h,
                                                 const float* __restrict__ wp,
                                                 const float* __restrict__ fcb,
                                                 float* __restrict__ logits) {
    __shared__ float hs[256];
    const int ct = blockIdx.x, b = blockIdx.y;
    const int tid = threadIdx.x;

    hs[tid] = h[b * 256 + tid];
    __syncthreads();

    const int o = ct * 256 + tid;
    const float* WT = wp + OFF_FCT + o;
    float a0 = 0.0f, a1 = 0.0f, a2 = 0.0f, a3 = 0.0f;
#pragma unroll 16
    for (int k = 0; k < 256; k += 4) {
        a0 = fmaf(hs[k + 0], __ldg(WT + (k + 0) * 1024), a0);
        a1 = fmaf(hs[k + 1], __ldg(WT + (k + 1) * 1024), a1);
        a2 = fmaf(hs[k + 2], __ldg(WT + (k + 2) * 1024), a2);
        a3 = fmaf(hs[k + 3], __ldg(WT + (k + 3) * 1024), a3);
    }
    logits[b * 1024 + o] = (a0 + a1) + (a2 + a3) + __ldg(fcb + o);
}

// ---------------------------------------------------------------------------
// Softmax: grid=64, 512 threads, 2 elements per thread.
// ---------------------------------------------------------------------------
__global__ void __launch_bounds__(512) softmax_kernel(const float* __restrict__ logits,
                                                      float* __restrict__ out) {
    __shared__ float red[16];
    const int b = blockIdx.x, tid = threadIdx.x, wid = tid >> 5, lid = tid & 31;
    const float* row = logits + b * 1024;

    float v0 = row[tid], v1 = row[512 + tid];
    float mx = fmaxf(v0, v1);
#pragma unroll
    for (int o = 16; o; o >>= 1) mx = fmaxf(mx, __shfl_xor_sync(0xFFFFFFFFu, mx, o));
    if (lid == 0) red[wid] = mx;
    __syncthreads();
    mx = red[0];
#pragma unroll
    for (int w = 1; w < 16; ++w) mx = fmaxf(mx, red[w]);
    __syncthreads();

    float e0 = __expf(v0 - mx), e1 = __expf(v1 - mx);
    float ps = e0 + e1;
#pragma unroll
    for (int o = 16; o; o >>= 1) ps += __shfl_xor_sync(0xFFFFFFFFu, ps, o);
    if (lid == 0) red[wid] = ps;
    __syncthreads();
    float tot = 0.0f;
#pragma unroll
    for (int w = 0; w < 16; ++w) tot += red[w];
    float inv = 1.0f / tot;
    out[b * 1024 + tid] = e0 * inv;
    out[b * 1024 + 512 + tid] = e1 * inv;
}

// ---------------------------------------------------------------------------
extern "C" void kernel_launch(void* const* d_in, const int* in_sizes, int n_in,
                              void* d_out, int out_size) {
    (void)in_sizes; (void)n_in; (void)out_size;

    const float* x = (const float*)d_in[0];
    const float* w[7];
    const float* bi[7];
    const float* gg[7];
    const float* bb[7];
    for (int L = 1; L <= 6; ++L) {
        w[L]  = (const float*)d_in[1 + 4 * (L - 1) + 0];
        bi[L] = (const float*)d_in[1 + 4 * (L - 1) + 1];
        gg[L] = (const float*)d_in[1 + 4 * (L - 1) + 2];
        bb[L] = (const float*)d_in[1 + 4 * (L - 1) + 3];
    }
    const float* fcw = (const float*)d_in[25];
    const float* fcb = (const float*)d_in[26];
    float* out = (float*)d_out;

    float *c1, *o2, *o3, *h, *lg, *wp;
    float2 *p1, *p2, *p3;
    cudaGetSymbolAddress((void**)&c1, g_conv1);
    cudaGetSymbolAddress((void**)&o2, g_out2);
    cudaGetSymbolAddress((void**)&o3, g_out3);
    cudaGetSymbolAddress((void**)&h, g_h);
    cudaGetSymbolAddress((void**)&lg, g_logits);
    cudaGetSymbolAddress((void**)&wp, g_wpack);
    cudaGetSymbolAddress((void**)&p1, g_part1);
    cudaGetSymbolAddress((void**)&p2, g_part2);
    cudaGetSymbolAddress((void**)&p3, g_part3);

    repack_kernel<<<256, 256>>>(w[1], w[2], w[3], w[4], w[5], w[6], fcw, wp);
    conv1_kernel<<<dim3(64, 8), 256>>>(x, wp, bi[1], c1, p1);
    conv2k_kernel<<<dim3(16, 16), 256>>>(c1, p1, gg[1], bb[1], wp, bi[2], o2, p2);
    conv3k_kernel<<<dim3(16, 16), 256>>>(o2, p2, gg[2], bb[2], wp, bi[3], o3, p3);
    tail_kernel<<<64, MT>>>(o3, p3, gg[3], bb[3], wp,
                            bi[4], gg[4], bb[4],
                            bi[5], gg[5], bb[5],
                            bi[6], gg[6], bb[6],
                            h);
    fc_kernel<<<dim3(4, 64), 256>>>(h, wp, fcb, lg);
    softmax_kernel<<<64, 512>>>(lg, out);
}

// round 14
// speedup vs baseline: 1.5048x; 1.5048x over previous
#include <cuda_runtime.h>
#include <math_constants.h>

#define BATCH 64

// scratch
__device__ float g_conv1[BATCH * 16384];
__device__ float g_out2[BATCH * 4096];
__device__ float g_out3[BATCH * 4096];
__device__ float g_h[BATCH * 256];
__device__ float g_logits[BATCH * 1024];
__device__ float g_wpack[1141760];
__device__ float2 g_part1[BATCH * 64];
__device__ float2 g_part2[BATCH * 16];
__device__ float2 g_part3[BATCH * 16];

// packed-weight offsets (floats). Layout: [k-group][pos][4] so adjacent
// positions are 16B apart -> warp LDG.128 touches 4 lines, not 32.
#define OFF_W1 0          // 13 groups x 16384 x 4 = 851968
#define OFF_W2 851968     // 7 x 4096 x 4 = 114688
#define OFF_W3 966656     // 7 x 4096 x 4 = 114688
#define OFF_W4 1081344    // 3 x 1024 x 4 = 12288
#define OFF_W5 1093632    // 3 x 1024 x 4 = 12288
#define OFF_W6 1105920    // 3 x 256 x 4 = 3072

// ---------------------------------------------------------------------------
__global__ void repack_kernel(const float* __restrict__ w1, const float* __restrict__ w2,
                              const float* __restrict__ w3, const float* __restrict__ w4,
                              const float* __restrict__ w5, const float* __restrict__ w6,
                              float* __restrict__ wp) {
    int tid = blockIdx.x * blockDim.x + threadIdx.x;
    int nt = gridDim.x * blockDim.x;
    for (int i = tid; i < 16384 * 49; i += nt) {
        int p = i / 49, k = i - p * 49;
        wp[OFF_W1 + ((k >> 2) * 16384 + p) * 4 + (k & 3)] = w1[i];
    }
    for (int i = tid; i < 4096 * 25; i += nt) {
        int p = i / 25, k = i - p * 25;
        wp[OFF_W2 + ((k >> 2) * 4096 + p) * 4 + (k & 3)] = w2[i];
    }
    for (int i = tid; i < 4096 * 25; i += nt) {
        int p = i / 25, k = i - p * 25;
        wp[OFF_W3 + ((k >> 2) * 4096 + p) * 4 + (k & 3)] = w3[i];
    }
    for (int i = tid; i < 1024 * 9; i += nt) {
        int p = i / 9, k = i - p * 9;
        wp[OFF_W4 + ((k >> 2) * 1024 + p) * 4 + (k & 3)] = w4[i];
    }
    for (int i = tid; i < 1024 * 9; i += nt) {
        int p = i / 9, k = i - p * 9;
        wp[OFF_W5 + ((k >> 2) * 1024 + p) * 4 + (k & 3)] = w5[i];
    }
    for (int i = tid; i < 256 * 9; i += nt) {
        int p = i / 9, k = i - p * 9;
        wp[OFF_W6 + ((k >> 2) * 256 + p) * 4 + (k & 3)] = w6[i];
    }
}

// ---------------------------------------------------------------------------
// Conv1: 128x128, K=7, pad=3, + ReLU. Block = 8x32 tile x 8-batch group.
// Grid (64,8), 256 threads.  (R12 state)
// ---------------------------------------------------------------------------
__global__ void __launch_bounds__(256) conv1_kernel(const float* __restrict__ x,
                                                    const float* __restrict__ wp,
                                                    const float* __restrict__ b1,
                                                    float* __restrict__ out,
                                                    float2* __restrict__ part1) {
    __shared__ float sm[8][14][40];
    __shared__ float rs[8][8], rq[8][8];
    const int tile = blockIdx.x;
    const int bg = blockIdx.y;
    const int tx = tile & 3, ty = tile >> 2;
    const int tj0 = tx * 32, ti0 = ty * 8;
    const int tid = threadIdx.x;

    for (int e = tid; e < 1120; e += 256) {
        int bb = e / 140;
        int rem = e - bb * 140;
        int r = rem / 10, k = rem - r * 10;
        int gi = ti0 - 3 + r;
        int c = tj0 - 4 + 4 * k;
        float4 v = make_float4(0.f, 0.f, 0.f, 0.f);
        if ((unsigned)gi < 128u && (unsigned)c <= 124u)
            v = *(const float4*)(x + (bg * 8 + bb) * 16384 + gi * 128 + c);
        *(float4*)(&sm[bb][r][4 * k]) = v;
    }

    const int ti = tid >> 5, tj = tid & 31;
    const int p = (ti0 + ti) * 128 + (tj0 + tj);
    float4 wreg[13];
    const float4* wv = (const float4*)(wp + OFF_W1);
#pragma unroll
    for (int t = 0; t < 13; ++t) wreg[t] = __ldg(wv + t * 16384 + p);
    const float* wf = (const float*)wreg;
    const float bias = __ldg(b1 + p);
    __syncthreads();

    float r8[8];
#pragma unroll
    for (int bb = 0; bb < 8; bb += 4) {
        float a0 = bias, a1 = bias, a2 = bias, a3 = bias;
#pragma unroll
        for (int u = 0; u < 7; ++u)
#pragma unroll
            for (int v = 0; v < 7; ++v) {
                float wvv = wf[u * 7 + v];
                a0 = fmaf(sm[bb + 0][ti + u][tj + v + 1], wvv, a0);
                a1 = fmaf(sm[bb + 1][ti + u][tj + v + 1], wvv, a1);
                a2 = fmaf(sm[bb + 2][ti + u][tj + v + 1], wvv, a2);
                a3 = fmaf(sm[bb + 3][ti + u][tj + v + 1], wvv, a3);
            }
        r8[bb + 0] = fmaxf(a0, 0.0f);
        r8[bb + 1] = fmaxf(a1, 0.0f);
        r8[bb + 2] = fmaxf(a2, 0.0f);
        r8[bb + 3] = fmaxf(a3, 0.0f);
    }
#pragma unroll
    for (int bb = 0; bb < 8; ++bb)
        out[(bg * 8 + bb) * 16384 + p] = r8[bb];

    const int wid = tid >> 5, lid = tid & 31;
#pragma unroll
    for (int s = 0; s < 8; ++s) {
        float v = r8[s], q = v * v;
#pragma unroll
        for (int o = 16; o; o >>= 1) {
            v += __shfl_down_sync(0xFFFFFFFFu, v, o);
            q += __shfl_down_sync(0xFFFFFFFFu, q, o);
        }
        if (lid == 0) { rs[wid][s] = v; rq[wid][s] = q; }
    }
    __syncthreads();
    if (tid < 8) {
        float s_ = 0.0f, q_ = 0.0f;
#pragma unroll
        for (int w = 0; w < 8; ++w) { s_ += rs[w][tid]; q_ += rq[w][tid]; }
        part1[(bg * 8 + tid) * 64 + tile] = make_float2(s_, q_);
    }
}

// ---------------------------------------------------------------------------
// conv2k: LN1(+g1,be1) + 2x2 pool on the fly, then conv2 (64x64, K=5).
// Grid (16 tiles, 32 groups of 2 samples), 256 threads: 1 position x 2
// samples per thread. Small smem -> many co-resident blocks.
// ---------------------------------------------------------------------------
__global__ void __launch_bounds__(256) conv2k_kernel(const float* __restrict__ c1,
                                                     const float2* __restrict__ part1,
                                                     const float* __restrict__ g1,
                                                     const float* __restrict__ be1,
                                                     const float* __restrict__ wp,
                                                     const float* __restrict__ b2,
                                                     float* __restrict__ out2,
                                                     float2* __restrict__ part2) {
    __shared__ float Gs[40][40], Bs[40][40];
    __shared__ float P[2][20][24];
    __shared__ float2 stats[2];
    __shared__ float rs[8][2], rq[8][2];
    const int tile = blockIdx.x, bg = blockIdx.y;   // bg: 32 groups of 2
    const int oj0 = (tile & 3) * 16, oi0 = (tile >> 2) * 16;
    const int tid = threadIdx.x, wid = tid >> 5, lid = tid & 31;

    // LN1 stats: warps 0-1 reduce sample bg*2+wid over 64 tile-partials
    if (wid < 2) {
        int s = bg * 2 + wid;
        float2 a = __ldg(&part1[s * 64 + lid]);
        float2 b = __ldg(&part1[s * 64 + 32 + lid]);
        float sum = a.x + b.x, ssq = a.y + b.y;
#pragma unroll
        for (int o = 16; o; o >>= 1) {
            sum += __shfl_down_sync(0xFFFFFFFFu, sum, o);
            ssq += __shfl_down_sync(0xFFFFFFFFu, ssq, o);
        }
        if (lid == 0) {
            float mu = sum * (1.0f / 16384.0f);
            float var = ssq * (1.0f / 16384.0f) - mu * mu;
            stats[wid] = make_float2(mu, rsqrtf(var + 1e-5f));
        }
    }
    for (int e = tid; e < 800; e += 256) {
        int arr = e / 400;
        int rem = e - arr * 400;
        int q = rem / 10, k = rem - q * 10;
        int gi = 2 * oi0 - 4 + q;
        int c = 2 * oj0 - 4 + 4 * k;
        float4 v = make_float4(0.f, 0.f, 0.f, 0.f);
        if ((unsigned)gi < 128u && (unsigned)c <= 124u)
            v = *(const float4*)((arr ? be1 : g1) + gi * 128 + c);
        if (arr) *(float4*)(&Bs[q][4 * k]) = v;
        else     *(float4*)(&Gs[q][4 * k]) = v;
    }
    __syncthreads();

    // build pooled-normalized P[2][20][20] (cols padded to 24)
    for (int e = tid; e < 400; e += 256) {
        int sIdx = e / 200;
        int rem = e - sIdx * 200;
        int pr = rem / 10, g = rem - pr * 10;
        int pi = oi0 - 2 + pr;
        int pjA = oj0 - 2 + 2 * g;
        float pv0 = 0.0f, pv1 = 0.0f;
        if ((unsigned)pi < 64u && (unsigned)pjA < 63u) {
            float mu = stats[sIdx].x, rstd = stats[sIdx].y;
            int r0 = 2 * pi, c0 = 2 * pjA;
            const float* base = c1 + (bg * 2 + sIdx) * 16384;
            float4 x0 = *(const float4*)(base + r0 * 128 + c0);
            float4 x1 = *(const float4*)(base + (r0 + 1) * 128 + c0);
            int qr = 2 * pr;
            const float* G0 = &Gs[qr][4 * g];
            const float* G1 = &Gs[qr + 1][4 * g];
            const float* B0 = &Bs[qr][4 * g];
            const float* B1 = &Bs[qr + 1][4 * g];
            float n00 = (x0.x - mu) * rstd * G0[0] + B0[0];
            float n01 = (x0.y - mu) * rstd * G0[1] + B0[1];
            float n10 = (x1.x - mu) * rstd * G1[0] + B1[0];
            float n11 = (x1.y - mu) * rstd * G1[1] + B1[1];
            pv0 = fmaxf(fmaxf(n00, n01), fmaxf(n10, n11));
            float m02 = (x0.z - mu) * rstd * G0[2] + B0[2];
            float m03 = (x0.w - mu) * rstd * G0[3] + B0[3];
            float m12 = (x1.z - mu) * rstd * G1[2] + B1[2];
            float m13 = (x1.w - mu) * rstd * G1[3] + B1[3];
            pv1 = fmaxf(fmaxf(m02, m03), fmaxf(m12, m13));
        }
        P[sIdx][pr][2 * g] = pv0;
        P[sIdx][pr][2 * g + 1] = pv1;
    }
    __syncthreads();

    const int ti = tid >> 4, tj = tid & 15;
    const int p = (oi0 + ti) * 64 + (oj0 + tj);
    float4 wq[7];
    const float4* wvp = (const float4*)(wp + OFF_W2);
#pragma unroll
    for (int t = 0; t < 7; ++t) wq[t] = __ldg(wvp + t * 4096 + p);
    const float* wf = (const float*)wq;
    const float bias = __ldg(b2 + p);

    float outv[2];
#pragma unroll
    for (int s = 0; s < 2; ++s) {
        float acc = bias;
#pragma unroll
        for (int u = 0; u < 5; ++u)
#pragma unroll
            for (int v = 0; v < 5; ++v)
                acc = fmaf(P[s][ti + u][tj + v], wf[u * 5 + v], acc);
        outv[s] = fmaxf(acc, 0.0f);
        out2[(bg * 2 + s) * 4096 + p] = outv[s];
    }
#pragma unroll
    for (int s = 0; s < 2; ++s) {
        float v = outv[s], q = v * v;
#pragma unroll
        for (int o = 16; o; o >>= 1) {
            v += __shfl_down_sync(0xFFFFFFFFu, v, o);
            q += __shfl_down_sync(0xFFFFFFFFu, q, o);
        }
        if (lid == 0) { rs[wid][s] = v; rq[wid][s] = q; }
    }
    __syncthreads();
    if (tid < 2) {
        float s_ = 0.0f, q_ = 0.0f;
#pragma unroll
        for (int w = 0; w < 8; ++w) { s_ += rs[w][tid]; q_ += rq[w][tid]; }
        part2[(bg * 2 + tid) * 16 + tile] = make_float2(s_, q_);
    }
}

// ---------------------------------------------------------------------------
// conv3k: LN2(+g2,be2) on the fly, conv3 (64x64, K=5).
// Grid (16, 32 groups of 2), 256 threads: 1 position x 2 samples.
// ---------------------------------------------------------------------------
__global__ void __launch_bounds__(256) conv3k_kernel(const float* __restrict__ in2,
                                                     const float2* __restrict__ part2,
                                                     const float* __restrict__ g2,
                                                     const float* __restrict__ be2,
                                                     const float* __restrict__ wp,
                                                     const float* __restrict__ b3,
                                                     float* __restrict__ out3,
                                                     float2* __restrict__ part3) {
    __shared__ float N[2][20][24];
    __shared__ float Gs2[20][24], Bs2[20][24];
    __shared__ float2 stats[2];
    __shared__ float rs[8][2], rq[8][2];
    const int tile = blockIdx.x, bg = blockIdx.y;
    const int oj0 = (tile & 3) * 16, oi0 = (tile >> 2) * 16;
    const int tid = threadIdx.x, wid = tid >> 5, lid = tid & 31;

    if (wid < 2) {
        int s = bg * 2 + wid;
        float2 a = (lid < 16) ? __ldg(&part2[s * 16 + lid]) : make_float2(0.f, 0.f);
        float sum = a.x, ssq = a.y;
#pragma unroll
        for (int o = 16; o; o >>= 1) {
            sum += __shfl_down_sync(0xFFFFFFFFu, sum, o);
            ssq += __shfl_down_sync(0xFFFFFFFFu, ssq, o);
        }
        if (lid == 0) {
            float mu = sum * (1.0f / 4096.0f);
            float var = ssq * (1.0f / 4096.0f) - mu * mu;
            stats[wid] = make_float2(mu, rsqrtf(var + 1e-5f));
        }
    }
    for (int e = tid; e < 240; e += 256) {
        int arr = e / 120;
        int rem = e - arr * 120;
        int q = rem / 6, k = rem - q * 6;
        int ri = oi0 - 2 + q;
        int c = oj0 - 4 + 4 * k;
        float4 v = make_float4(0.f, 0.f, 0.f, 0.f);
        if ((unsigned)ri < 64u && (unsigned)c <= 60u)
            v = *(const float4*)((arr ? be2 : g2) + ri * 64 + c);
        if (arr) *(float4*)(&Bs2[q][4 * k]) = v;
        else     *(float4*)(&Gs2[q][4 * k]) = v;
    }
    __syncthreads();

    for (int e = tid; e < 240; e += 256) {
        int sIdx = e / 120;
        int rem = e - sIdx * 120;
        int q = rem / 6, k = rem - q * 6;
        int ri = oi0 - 2 + q;
        int c = oj0 - 4 + 4 * k;
        float4 nv = make_float4(0.f, 0.f, 0.f, 0.f);
        if ((unsigned)ri < 64u && (unsigned)c <= 60u) {
            float mu = stats[sIdx].x, rstd = stats[sIdx].y;
            float4 xv = *(const float4*)(in2 + (bg * 2 + sIdx) * 4096 + ri * 64 + c);
            const float* G = &Gs2[q][4 * k];
            const float* B = &Bs2[q][4 * k];
            nv.x = (xv.x - mu) * rstd * G[0] + B[0];
            nv.y = (xv.y - mu) * rstd * G[1] + B[1];
            nv.z = (xv.z - mu) * rstd * G[2] + B[2];
            nv.w = (xv.w - mu) * rstd * G[3] + B[3];
        }
        *(float4*)(&N[sIdx][q][4 * k]) = nv;
    }
    __syncthreads();

    const int ti = tid >> 4, tj = tid & 15;
    const int p = (oi0 + ti) * 64 + (oj0 + tj);
    float4 wq[7];
    const float4* wvp = (const float4*)(wp + OFF_W3);
#pragma unroll
    for (int t = 0; t < 7; ++t) wq[t] = __ldg(wvp + t * 4096 + p);
    const float* wf = (const float*)wq;
    const float bias = __ldg(b3 + p);

    float outv[2];
#pragma unroll
    for (int s = 0; s < 2; ++s) {
        float acc = bias;
#pragma unroll
        for (int u = 0; u < 5; ++u)
#pragma unroll
            for (int v = 0; v < 5; ++v)
                acc = fmaf(N[s][ti + u][tj + v + 2], wf[u * 5 + v], acc);
        outv[s] = fmaxf(acc, 0.0f);
        out3[(bg * 2 + s) * 4096 + p] = outv[s];
    }
#pragma unroll
    for (int s = 0; s < 2; ++s) {
        float v = outv[s], q = v * v;
#pragma unroll
        for (int o = 16; o; o >>= 1) {
            v += __shfl_down_sync(0xFFFFFFFFu, v, o);
            q += __shfl_down_sync(0xFFFFFFFFu, q, o);
        }
        if (lid == 0) { rs[wid][s] = v; rq[wid][s] = q; }
    }
    __syncthreads();
    if (tid < 2) {
        float s_ = 0.0f, q_ = 0.0f;
#pragma unroll
        for (int w = 0; w < 8; ++w) { s_ += rs[w][tid]; q_ += rq[w][tid]; }
        part3[(bg * 2 + tid) * 16 + tile] = make_float2(s_, q_);
    }
}

// ---------------------------------------------------------------------------
__device__ __forceinline__ float2 bstats(float s, float ss) {
    __shared__ float r0[32], r1[32];
    int tid = threadIdx.x, wid = tid >> 5, lid = tid & 31;
#pragma unroll
    for (int o = 16; o; o >>= 1) {
        s += __shfl_down_sync(0xFFFFFFFFu, s, o);
        ss += __shfl_down_sync(0xFFFFFFFFu, ss, o);
    }
    if (lid == 0) { r0[wid] = s; r1[wid] = ss; }
    __syncthreads();
    if (wid == 0) {
        s = r0[lid];
        ss = r1[lid];
#pragma unroll
        for (int o = 16; o; o >>= 1) {
            s += __shfl_down_sync(0xFFFFFFFFu, s, o);
            ss += __shfl_down_sync(0xFFFFFFFFu, ss, o);
        }
        if (lid == 0) { r0[0] = s; r1[0] = ss; }
    }
    __syncthreads();
    float2 res = make_float2(r0[0], r1[0]);
    __syncthreads();
    return res;
}

// ---------------------------------------------------------------------------
// tail: LN3+pool -> conv4 -> LN4 -> conv5 -> LN5+pool -> conv6 -> LN6 -> h.
// Block per sample (grid=64, 1024 threads).  (R12 state)
// ---------------------------------------------------------------------------
#define MT 1024
__global__ void __launch_bounds__(MT) tail_kernel(
    const float* __restrict__ in3, const float2* __restrict__ part3,
    const float* __restrict__ g3, const float* __restrict__ be3,
    const float* __restrict__ wp,
    const float* __restrict__ b4, const float* __restrict__ g4, const float* __restrict__ be4,
    const float* __restrict__ b5, const float* __restrict__ g5, const float* __restrict__ be5,
    const float* __restrict__ b6, const float* __restrict__ g6, const float* __restrict__ be6,
    float* __restrict__ hout) {
    __shared__ float SA[1156], SB[1156];
    __shared__ float2 st3;
    const int tid = threadIdx.x;
    const int b = blockIdx.x;

    for (int e = tid; e < 2312; e += MT) (e < 1156 ? SA : SB - 1156)[e] = 0.0f;
    if (tid < 32) {
        float2 a = (tid < 16) ? __ldg(&part3[b * 16 + tid]) : make_float2(0.f, 0.f);
        float sum = a.x, ssq = a.y;
#pragma unroll
        for (int o = 16; o; o >>= 1) {
            sum += __shfl_down_sync(0xFFFFFFFFu, sum, o);
            ssq += __shfl_down_sync(0xFFFFFFFFu, ssq, o);
        }
        if (tid == 0) {
            float mu = sum * (1.0f / 4096.0f);
            float var = ssq * (1.0f / 4096.0f) - mu * mu;
            st3 = make_float2(mu, rsqrtf(var + 1e-5f));
        }
    }
    __syncthreads();

    {
        float mu = st3.x, rstd = st3.y;
        const float* base = in3 + b * 4096;
        for (int e = tid; e < 512; e += MT) {
            int pr = e >> 4, g = e & 15;
            int r0 = 2 * pr, c = 4 * g;
            float4 x0 = *(const float4*)(base + r0 * 64 + c);
            float4 x1 = *(const float4*)(base + (r0 + 1) * 64 + c);
            float4 G0 = *(const float4*)(g3 + r0 * 64 + c);
            float4 G1 = *(const float4*)(g3 + (r0 + 1) * 64 + c);
            float4 B0 = *(const float4*)(be3 + r0 * 64 + c);
            float4 B1 = *(const float4*)(be3 + (r0 + 1) * 64 + c);
            float n00 = (x0.x - mu) * rstd * G0.x + B0.x;
            float n01 = (x0.y - mu) * rstd * G0.y + B0.y;
            float n10 = (x1.x - mu) * rstd * G1.x + B1.x;
            float n11 = (x1.y - mu) * rstd * G1.y + B1.y;
            SB[(pr + 1) * 34 + 2 * g + 1] = fmaxf(fmaxf(n00, n01), fmaxf(n10, n11));
            float m02 = (x0.z - mu) * rstd * G0.z + B0.z;
            float m03 = (x0.w - mu) * rstd * G0.w + B0.w;
            float m12 = (x1.z - mu) * rstd * G1.z + B1.z;
            float m13 = (x1.w - mu) * rstd * G1.w + B1.w;
            SB[(pr + 1) * 34 + 2 * g + 2] = fmaxf(fmaxf(m02, m03), fmaxf(m12, m13));
        }
    }
    __syncthreads();

    // conv4
    float s = 0.0f, ss = 0.0f;
    for (int e = tid; e < 1156; e += MT) {
        int i34 = e / 34, j34 = e - i34 * 34;
        if (i34 == 0 || i34 == 33 || j34 == 0 || j34 == 33) { SA[e] = 0.0f; continue; }
        int io = i34 - 1, jo = j34 - 1;
        int p = io * 32 + jo;
        float4 wq[3];
        const float4* wv4 = (const float4*)(wp + OFF_W4);
#pragma unroll
        for (int t = 0; t < 3; ++t) wq[t] = __ldg(wv4 + t * 1024 + p);
        const float* wf = (const float*)wq;
        const float* src = SB + io * 34 + jo;
        float acc = __ldg(b4 + p);
#pragma unroll
        for (int u = 0; u < 3; ++u)
#pragma unroll
            for (int v = 0; v < 3; ++v)
                acc = fmaf(src[u * 34 + v], wf[u * 3 + v], acc);
        acc = fmaxf(acc, 0.0f);
        SA[e] = acc;
        s += acc; ss += acc * acc;
    }
    float2 st = bstats(s, ss);
    float mu = st.x * (1.0f / 1024.0f);
    float rstd = rsqrtf(st.y * (1.0f / 1024.0f) - mu * mu + 1e-5f);
    for (int p = tid; p < 1024; p += MT) {
        int idx = ((p >> 5) + 1) * 34 + (p & 31) + 1;
        SA[idx] = (SA[idx] - mu) * rstd * __ldg(g4 + p) + __ldg(be4 + p);
    }
    __syncthreads();

    // conv5
    s = ss = 0.0f;
    for (int p = tid; p < 1024; p += MT) {
        int i = p >> 5, j = p & 31;
        float4 wq[3];
        const float4* wv5 = (const float4*)(wp + OFF_W5);
#pragma unroll
        for (int t = 0; t < 3; ++t) wq[t] = __ldg(wv5 + t * 1024 + p);
        const float* wf = (const float*)wq;
        const float* src = SA + i * 34 + j;
        float acc = __ldg(b5 + p);
#pragma unroll
        for (int u = 0; u < 3; ++u)
#pragma unroll
            for (int v = 0; v < 3; ++v)
                acc = fmaf(src[u * 34 + v], wf[u * 3 + v], acc);
        acc = fmaxf(acc, 0.0f);
        SB[(i + 1) * 34 + j + 1] = acc;
        s += acc; ss += acc * acc;
    }
    st = bstats(s, ss);
    mu = st.x * (1.0f / 1024.0f);
    rstd = rsqrtf(st.y * (1.0f / 1024.0f) - mu * mu + 1e-5f);
    for (int e = tid; e < 324; e += MT) {
        int i18 = e / 18, j18 = e - i18 * 18;
        if (i18 == 0 || i18 == 17 || j18 == 0 || j18 == 17) { SA[e] = 0.0f; continue; }
        int io = i18 - 1, jo = j18 - 1;
        float m = -CUDART_INF_F;
#pragma unroll
        for (int di = 0; di < 2; ++di)
#pragma unroll
            for (int dj = 0; dj < 2; ++dj) {
                int gi = 2 * io + di, gj = 2 * jo + dj;
                int q = gi * 32 + gj;
                float v = (SB[(gi + 1) * 34 + gj + 1] - mu) * rstd * __ldg(g5 + q) + __ldg(be5 + q);
                m = fmaxf(m, v);
            }
        SA[e] = m;
    }
    __syncthreads();

    // conv6
    s = ss = 0.0f;
    for (int p = tid; p < 256; p += MT) {
        int i = p >> 4, j = p & 15;
        float4 wq[3];
        const float4* wv6 = (const float4*)(wp + OFF_W6);
#pragma unroll
        for (int t = 0; t < 3; ++t) wq[t] = __ldg(wv6 + t * 256 + p);
        const float* wf = (const float*)wq;
        const float* src = SA + i * 18 + j;
        float acc = __ldg(b6 + p);
#pragma unroll
        for (int u = 0; u < 3; ++u)
#pragma unroll
            for (int v = 0; v < 3; ++v)
                acc = fmaf(src[u * 18 + v], wf[u * 3 + v], acc);
        acc = fmaxf(acc, 0.0f);
        SB[p] = acc;
        s += acc; ss += acc * acc;
    }
    st = bstats(s, ss);
    mu = st.x * (1.0f / 256.0f);
    rstd = rsqrtf(st.y * (1.0f / 256.0f) - mu * mu + 1e-5f);
    for (int p = tid; p < 256; p += MT)
        hout[b * 256 + p] = (SB[p] - mu) * rstd * __ldg(g6 + p) + __ldg(be6 + p);
}

// ---------------------------------------------------------------------------
// FC: grid (32 col-tiles, 16 row-groups of 4 rows), 256 threads. (R12 state)
// ---------------------------------------------------------------------------
__global__ void __launch_bounds__(256) fc_kernel(const float* __restrict__ h,
                                                 const float* __restrict__ fcw,
                                                 const float* __restrict__ fcb,
                                                 float* __restrict__ logits) {
    __shared__ float hs[4 * 256];
    const int ct = blockIdx.x, rg = blockIdx.y;
    const int tid = threadIdx.x, wid = tid >> 5, lid = tid & 31;

    for (int e = tid; e < 1024; e += 256) hs[e] = h[rg * 1024 + e];
    __syncthreads();

    float hr[4][8];
#pragma unroll
    for (int r = 0; r < 4; ++r)
#pragma unroll
        for (int c = 0; c < 8; ++c) hr[r][c] = hs[r * 256 + lid * 8 + c];

    const int obase = ct * 32 + wid * 4;
#pragma unroll
    for (int t = 0; t < 4; ++t) {
        int o = obase + t;
        const float4* wr = (const float4*)(fcw + o * 256 + lid * 8);
        float4 wa = __ldg(wr), wb = __ldg(wr + 1);
        float a[4];
#pragma unroll
        for (int r = 0; r < 4; ++r) {
            a[r] = hr[r][0] * wa.x + hr[r][1] * wa.y + hr[r][2] * wa.z + hr[r][3] * wa.w
                 + hr[r][4] * wb.x + hr[r][5] * wb.y + hr[r][6] * wb.z + hr[r][7] * wb.w;
        }
#pragma unroll
        for (int r = 0; r < 4; ++r)
#pragma unroll
            for (int off = 16; off; off >>= 1) a[r] += __shfl_down_sync(0xFFFFFFFFu, a[r], off);
        if (lid == 0) {
            float bo = __ldg(fcb + o);
#pragma unroll
            for (int r = 0; r < 4; ++r) logits[(rg * 4 + r) * 1024 + o] = a[r] + bo;
        }
    }
}

// ---------------------------------------------------------------------------
// Softmax: grid=64, 512 threads, 2 elements per thread.  (R12 state)
// ---------------------------------------------------------------------------
__global__ void __launch_bounds__(512) softmax_kernel(const float* __restrict__ logits,
                                                      float* __restrict__ out) {
    __shared__ float red[16];
    const int b = blockIdx.x, tid = threadIdx.x, wid = tid >> 5, lid = tid & 31;
    const float* row = logits + b * 1024;

    float v0 = row[tid], v1 = row[512 + tid];
    float mx = fmaxf(v0, v1);
#pragma unroll
    for (int o = 16; o; o >>= 1) mx = fmaxf(mx, __shfl_xor_sync(0xFFFFFFFFu, mx, o));
    if (lid == 0) red[wid] = mx;
    __syncthreads();
    mx = red[0];
#pragma unroll
    for (int w = 1; w < 16; ++w) mx = fmaxf(mx, red[w]);
    __syncthreads();

    float e0 = __expf(v0 - mx), e1 = __expf(v1 - mx);
    float ps = e0 + e1;
#pragma unroll
    for (int o = 16; o; o >>= 1) ps += __shfl_xor_sync(0xFFFFFFFFu, ps, o);
    if (lid == 0) red[wid] = ps;
    __syncthreads();
    float tot = 0.0f;
#pragma unroll
    for (int w = 0; w < 16; ++w) tot += red[w];
    float inv = 1.0f / tot;
    out[b * 1024 + tid] = e0 * inv;
    out[b * 1024 + 512 + tid] = e1 * inv;
}

// ---------------------------------------------------------------------------
extern "C" void kernel_launch(void* const* d_in, const int* in_sizes, int n_in,
                              void* d_out, int out_size) {
    (void)in_sizes; (void)n_in; (void)out_size;

    const float* x = (const float*)d_in[0];
    const float* w[7];
    const float* bi[7];
    const float* gg[7];
    const float* bb[7];
    for (int L = 1; L <= 6; ++L) {
        w[L]  = (const float*)d_in[1 + 4 * (L - 1) + 0];
        bi[L] = (const float*)d_in[1 + 4 * (L - 1) + 1];
        gg[L] = (const float*)d_in[1 + 4 * (L - 1) + 2];
        bb[L] = (const float*)d_in[1 + 4 * (L - 1) + 3];
    }
    const float* fcw = (const float*)d_in[25];
    const float* fcb = (const float*)d_in[26];
    float* out = (float*)d_out;

    float *c1, *o2, *o3, *h, *lg, *wp;
    float2 *p1, *p2, *p3;
    cudaGetSymbolAddress((void**)&c1, g_conv1);
    cudaGetSymbolAddress((void**)&o2, g_out2);
    cudaGetSymbolAddress((void**)&o3, g_out3);
    cudaGetSymbolAddress((void**)&h, g_h);
    cudaGetSymbolAddress((void**)&lg, g_logits);
    cudaGetSymbolAddress((void**)&wp, g_wpack);
    cudaGetSymbolAddress((void**)&p1, g_part1);
    cudaGetSymbolAddress((void**)&p2, g_part2);
    cudaGetSymbolAddress((void**)&p3, g_part3);

    repack_kernel<<<256, 256>>>(w[1], w[2], w[3], w[4], w[5], w[6], wp);
    conv1_kernel<<<dim3(64, 8), 256>>>(x, wp, bi[1], c1, p1);
    conv2k_kernel<<<dim3(16, 32), 256>>>(c1, p1, gg[1], bb[1], wp, bi[2], o2, p2);
    conv3k_kernel<<<dim3(16, 32), 256>>>(o2, p2, gg[2], bb[2], wp, bi[3], o3, p3);
    tail_kernel<<<64, MT>>>(o3, p3, gg[3], bb[3], wp,
                            bi[4], gg[4], bb[4],
                            bi[5], gg[5], bb[5],
                            bi[6], gg[6], bb[6],
                            h);
    fc_kernel<<<dim3(32, 16), 256>>>(h, fcw, fcb, lg);
    softmax_kernel<<<64, 512>>>(lg, out);
}

// round 16
// speedup vs baseline: 1.6308x; 1.0838x over previous
#include <cuda_runtime.h>
#include <math_constants.h>

#define BATCH 64

#define GDC_WAIT() asm volatile("griddepcontrol.wait;" ::: "memory")

// scratch
__device__ float g_conv1[BATCH * 16384];
__device__ float g_out2[BATCH * 4096];
__device__ float g_out3[BATCH * 4096];
__device__ float g_h[BATCH * 256];
__device__ float g_logits[BATCH * 1024];
__device__ float g_wpack[1141760];
__device__ float2 g_part1[BATCH * 64];
__device__ float2 g_part2[BATCH * 16];
__device__ float2 g_part3[BATCH * 16];

// packed-weight offsets (floats). Layout: [k-group][pos][4]
#define OFF_W1 0
#define OFF_W2 851968
#define OFF_W3 966656
#define OFF_W4 1081344
#define OFF_W5 1093632
#define OFF_W6 1105920

// ---------------------------------------------------------------------------
__global__ void repack_kernel(const float* __restrict__ w1, const float* __restrict__ w2,
                              const float* __restrict__ w3, const float* __restrict__ w4,
                              const float* __restrict__ w5, const float* __restrict__ w6,
                              float* __restrict__ wp) {
    int tid = blockIdx.x * blockDim.x + threadIdx.x;
    int nt = gridDim.x * blockDim.x;
    for (int i = tid; i < 16384 * 49; i += nt) {
        int p = i / 49, k = i - p * 49;
        wp[OFF_W1 + ((k >> 2) * 16384 + p) * 4 + (k & 3)] = w1[i];
    }
    for (int i = tid; i < 4096 * 25; i += nt) {
        int p = i / 25, k = i - p * 25;
        wp[OFF_W2 + ((k >> 2) * 4096 + p) * 4 + (k & 3)] = w2[i];
    }
    for (int i = tid; i < 4096 * 25; i += nt) {
        int p = i / 25, k = i - p * 25;
        wp[OFF_W3 + ((k >> 2) * 4096 + p) * 4 + (k & 3)] = w3[i];
    }
    for (int i = tid; i < 1024 * 9; i += nt) {
        int p = i / 9, k = i - p * 9;
        wp[OFF_W4 + ((k >> 2) * 1024 + p) * 4 + (k & 3)] = w4[i];
    }
    for (int i = tid; i < 1024 * 9; i += nt) {
        int p = i / 9, k = i - p * 9;
        wp[OFF_W5 + ((k >> 2) * 1024 + p) * 4 + (k & 3)] = w5[i];
    }
    for (int i = tid; i < 256 * 9; i += nt) {
        int p = i / 9, k = i - p * 9;
        wp[OFF_W6 + ((k >> 2) * 256 + p) * 4 + (k & 3)] = w6[i];
    }
}

// ---------------------------------------------------------------------------
// Conv1: prologue = stage x (harness input); wait; then read wp (repack out).
// Grid (64,8), 256 threads.
// ---------------------------------------------------------------------------
__global__ void __launch_bounds__(256) conv1_kernel(const float* __restrict__ x,
                                                    const float* __restrict__ wp,
                                                    const float* __restrict__ b1,
                                                    float* __restrict__ out,
                                                    float2* __restrict__ part1) {
    __shared__ float sm[8][14][40];
    __shared__ float rs[8][8], rq[8][8];
    const int tile = blockIdx.x;
    const int bg = blockIdx.y;
    const int tx = tile & 3, ty = tile >> 2;
    const int tj0 = tx * 32, ti0 = ty * 8;
    const int tid = threadIdx.x;

    // prologue: input staging (independent of repack)
    for (int e = tid; e < 1120; e += 256) {
        int bb = e / 140;
        int rem = e - bb * 140;
        int r = rem / 10, k = rem - r * 10;
        int gi = ti0 - 3 + r;
        int c = tj0 - 4 + 4 * k;
        float4 v = make_float4(0.f, 0.f, 0.f, 0.f);
        if ((unsigned)gi < 128u && (unsigned)c <= 124u)
            v = *(const float4*)(x + (bg * 8 + bb) * 16384 + gi * 128 + c);
        *(float4*)(&sm[bb][r][4 * k]) = v;
    }

    GDC_WAIT();   // repack must be complete before reading wp

    const int ti = tid >> 5, tj = tid & 31;
    const int p = (ti0 + ti) * 128 + (tj0 + tj);
    float4 wreg[13];
    const float4* wv = (const float4*)(wp + OFF_W1);
#pragma unroll
    for (int t = 0; t < 13; ++t) wreg[t] = __ldg(wv + t * 16384 + p);
    const float* wf = (const float*)wreg;
    const float bias = __ldg(b1 + p);
    __syncthreads();

    float r8[8];
#pragma unroll
    for (int bb = 0; bb < 8; bb += 4) {
        float a0 = bias, a1 = bias, a2 = bias, a3 = bias;
#pragma unroll
        for (int u = 0; u < 7; ++u)
#pragma unroll
            for (int v = 0; v < 7; ++v) {
                float wvv = wf[u * 7 + v];
                a0 = fmaf(sm[bb + 0][ti + u][tj + v + 1], wvv, a0);
                a1 = fmaf(sm[bb + 1][ti + u][tj + v + 1], wvv, a1);
                a2 = fmaf(sm[bb + 2][ti + u][tj + v + 1], wvv, a2);
                a3 = fmaf(sm[bb + 3][ti + u][tj + v + 1], wvv, a3);
            }
        r8[bb + 0] = fmaxf(a0, 0.0f);
        r8[bb + 1] = fmaxf(a1, 0.0f);
        r8[bb + 2] = fmaxf(a2, 0.0f);
        r8[bb + 3] = fmaxf(a3, 0.0f);
    }
#pragma unroll
    for (int bb = 0; bb < 8; ++bb)
        out[(bg * 8 + bb) * 16384 + p] = r8[bb];

    const int wid = tid >> 5, lid = tid & 31;
#pragma unroll
    for (int s = 0; s < 8; ++s) {
        float v = r8[s], q = v * v;
#pragma unroll
        for (int o = 16; o; o >>= 1) {
            v += __shfl_down_sync(0xFFFFFFFFu, v, o);
            q += __shfl_down_sync(0xFFFFFFFFu, q, o);
        }
        if (lid == 0) { rs[wid][s] = v; rq[wid][s] = q; }
    }
    __syncthreads();
    if (tid < 8) {
        float s_ = 0.0f, q_ = 0.0f;
#pragma unroll
        for (int w = 0; w < 8; ++w) { s_ += rs[w][tid]; q_ += rq[w][tid]; }
        part1[(bg * 8 + tid) * 64 + tile] = make_float2(s_, q_);
    }
}

// ---------------------------------------------------------------------------
// conv2k (R12 best config: bs=4). Prologue = weights + g/be staging; wait;
// then stats (part1) + pooled-normalize (c1). Grid (16,16), 256 threads.
// ---------------------------------------------------------------------------
__global__ void __launch_bounds__(256) conv2k_kernel(const float* __restrict__ c1,
                                                     const float2* __restrict__ part1,
                                                     const float* __restrict__ g1,
                                                     const float* __restrict__ be1,
                                                     const float* __restrict__ wp,
                                                     const float* __restrict__ b2,
                                                     float* __restrict__ out2,
                                                     float2* __restrict__ part2) {
    __shared__ float Gs[40][40], Bs[40][40];
    __shared__ float P[4][20][24];
    __shared__ float2 stats[4];
    __shared__ float rs[8][4], rq[8][4];
    const int tile = blockIdx.x, bg = blockIdx.y;
    const int oj0 = (tile & 3) * 16, oi0 = (tile >> 2) * 16;
    const int tid = threadIdx.x, wid = tid >> 5, lid = tid & 31;

    // prologue: weights (wp from repack, 2 launches back -> complete) + g/be
    const int ti = tid >> 4, tj = tid & 15;
    const int p = (oi0 + ti) * 64 + (oj0 + tj);
    float4 wq[7];
    const float4* wvp = (const float4*)(wp + OFF_W2);
#pragma unroll
    for (int t = 0; t < 7; ++t) wq[t] = __ldg(wvp + t * 4096 + p);
    const float* wf = (const float*)wq;
    const float bias = __ldg(b2 + p);

    for (int e = tid; e < 800; e += 256) {
        int arr = e / 400;
        int rem = e - arr * 400;
        int q = rem / 10, k = rem - q * 10;
        int gi = 2 * oi0 - 4 + q;
        int c = 2 * oj0 - 4 + 4 * k;
        float4 v = make_float4(0.f, 0.f, 0.f, 0.f);
        if ((unsigned)gi < 128u && (unsigned)c <= 124u)
            v = *(const float4*)((arr ? be1 : g1) + gi * 128 + c);
        if (arr) *(float4*)(&Bs[q][4 * k]) = v;
        else     *(float4*)(&Gs[q][4 * k]) = v;
    }

    GDC_WAIT();   // conv1 outputs (c1, part1) ready from here on

    // LN1 stats: warps 0-3 reduce sample bg*4+wid over 64 tile-partials
    if (wid < 4) {
        int s = bg * 4 + wid;
        float2 a = __ldg(&part1[s * 64 + lid]);
        float2 b = __ldg(&part1[s * 64 + 32 + lid]);
        float sum = a.x + b.x, ssq = a.y + b.y;
#pragma unroll
        for (int o = 16; o; o >>= 1) {
            sum += __shfl_down_sync(0xFFFFFFFFu, sum, o);
            ssq += __shfl_down_sync(0xFFFFFFFFu, ssq, o);
        }
        if (lid == 0) {
            float mu = sum * (1.0f / 16384.0f);
            float var = ssq * (1.0f / 16384.0f) - mu * mu;
            stats[wid] = make_float2(mu, rsqrtf(var + 1e-5f));
        }
    }
    __syncthreads();

    for (int e = tid; e < 800; e += 256) {
        int sIdx = e / 200;
        int rem = e - sIdx * 200;
        int pr = rem / 10, g = rem - pr * 10;
        int pi = oi0 - 2 + pr;
        int pjA = oj0 - 2 + 2 * g;
        float pv0 = 0.0f, pv1 = 0.0f;
        if ((unsigned)pi < 64u && (unsigned)pjA < 63u) {
            float mu = stats[sIdx].x, rstd = stats[sIdx].y;
            int r0 = 2 * pi, c0 = 2 * pjA;
            const float* base = c1 + (bg * 4 + sIdx) * 16384;
            float4 x0 = *(const float4*)(base + r0 * 128 + c0);
            float4 x1 = *(const float4*)(base + (r0 + 1) * 128 + c0);
            int qr = 2 * pr;
            const float* G0 = &Gs[qr][4 * g];
            const float* G1 = &Gs[qr + 1][4 * g];
            const float* B0 = &Bs[qr][4 * g];
            const float* B1 = &Bs[qr + 1][4 * g];
            float n00 = (x0.x - mu) * rstd * G0[0] + B0[0];
            float n01 = (x0.y - mu) * rstd * G0[1] + B0[1];
            float n10 = (x1.x - mu) * rstd * G1[0] + B1[0];
            float n11 = (x1.y - mu) * rstd * G1[1] + B1[1];
            pv0 = fmaxf(fmaxf(n00, n01), fmaxf(n10, n11));
            float m02 = (x0.z - mu) * rstd * G0[2] + B0[2];
            float m03 = (x0.w - mu) * rstd * G0[3] + B0[3];
            float m12 = (x1.z - mu) * rstd * G1[2] + B1[2];
            float m13 = (x1.w - mu) * rstd * G1[3] + B1[3];
            pv1 = fmaxf(fmaxf(m02, m03), fmaxf(m12, m13));
        }
        P[sIdx][pr][2 * g] = pv0;
        P[sIdx][pr][2 * g + 1] = pv1;
    }
    __syncthreads();

    float outv[4];
#pragma unroll
    for (int s = 0; s < 4; ++s) {
        float acc = bias;
#pragma unroll
        for (int u = 0; u < 5; ++u)
#pragma unroll
            for (int v = 0; v < 5; ++v)
                acc = fmaf(P[s][ti + u][tj + v], wf[u * 5 + v], acc);
        outv[s] = fmaxf(acc, 0.0f);
        out2[(bg * 4 + s) * 4096 + p] = outv[s];
    }
#pragma unroll
    for (int s = 0; s < 4; ++s) {
        float v = outv[s], q = v * v;
#pragma unroll
        for (int o = 16; o; o >>= 1) {
            v += __shfl_down_sync(0xFFFFFFFFu, v, o);
            q += __shfl_down_sync(0xFFFFFFFFu, q, o);
        }
        if (lid == 0) { rs[wid][s] = v; rq[wid][s] = q; }
    }
    __syncthreads();
    if (tid < 4) {
        float s_ = 0.0f, q_ = 0.0f;
#pragma unroll
        for (int w = 0; w < 8; ++w) { s_ += rs[w][tid]; q_ += rq[w][tid]; }
        part2[(bg * 4 + tid) * 16 + tile] = make_float2(s_, q_);
    }
}

// ---------------------------------------------------------------------------
// conv3k (R14 best config: bs=2). Prologue = weights + g2/be2 staging; wait;
// then stats (part2) + normalize (out2). Grid (16,32), 256 threads.
// ---------------------------------------------------------------------------
__global__ void __launch_bounds__(256) conv3k_kernel(const float* __restrict__ in2,
                                                     const float2* __restrict__ part2,
                                                     const float* __restrict__ g2,
                                                     const float* __restrict__ be2,
                                                     const float* __restrict__ wp,
                                                     const float* __restrict__ b3,
                                                     float* __restrict__ out3,
                                                     float2* __restrict__ part3) {
    __shared__ float N[2][20][24];
    __shared__ float Gs2[20][24], Bs2[20][24];
    __shared__ float2 stats[2];
    __shared__ float rs[8][2], rq[8][2];
    const int tile = blockIdx.x, bg = blockIdx.y;
    const int oj0 = (tile & 3) * 16, oi0 = (tile >> 2) * 16;
    const int tid = threadIdx.x, wid = tid >> 5, lid = tid & 31;

    // prologue
    const int ti = tid >> 4, tj = tid & 15;
    const int p = (oi0 + ti) * 64 + (oj0 + tj);
    float4 wq[7];
    const float4* wvp = (const float4*)(wp + OFF_W3);
#pragma unroll
    for (int t = 0; t < 7; ++t) wq[t] = __ldg(wvp + t * 4096 + p);
    const float* wf = (const float*)wq;
    const float bias = __ldg(b3 + p);

    for (int e = tid; e < 240; e += 256) {
        int arr = e / 120;
        int rem = e - arr * 120;
        int q = rem / 6, k = rem - q * 6;
        int ri = oi0 - 2 + q;
        int c = oj0 - 4 + 4 * k;
        float4 v = make_float4(0.f, 0.f, 0.f, 0.f);
        if ((unsigned)ri < 64u && (unsigned)c <= 60u)
            v = *(const float4*)((arr ? be2 : g2) + ri * 64 + c);
        if (arr) *(float4*)(&Bs2[q][4 * k]) = v;
        else     *(float4*)(&Gs2[q][4 * k]) = v;
    }

    GDC_WAIT();   // conv2k outputs ready

    if (wid < 2) {
        int s = bg * 2 + wid;
        float2 a = (lid < 16) ? __ldg(&part2[s * 16 + lid]) : make_float2(0.f, 0.f);
        float sum = a.x, ssq = a.y;
#pragma unroll
        for (int o = 16; o; o >>= 1) {
            sum += __shfl_down_sync(0xFFFFFFFFu, sum, o);
            ssq += __shfl_down_sync(0xFFFFFFFFu, ssq, o);
        }
        if (lid == 0) {
            float mu = sum * (1.0f / 4096.0f);
            float var = ssq * (1.0f / 4096.0f) - mu * mu;
            stats[wid] = make_float2(mu, rsqrtf(var + 1e-5f));
        }
    }
    __syncthreads();

    for (int e = tid; e < 240; e += 256) {
        int sIdx = e / 120;
        int rem = e - sIdx * 120;
        int q = rem / 6, k = rem - q * 6;
        int ri = oi0 - 2 + q;
        int c = oj0 - 4 + 4 * k;
        float4 nv = make_float4(0.f, 0.f, 0.f, 0.f);
        if ((unsigned)ri < 64u && (unsigned)c <= 60u) {
            float mu = stats[sIdx].x, rstd = stats[sIdx].y;
            float4 xv = *(const float4*)(in2 + (bg * 2 + sIdx) * 4096 + ri * 64 + c);
            const float* G = &Gs2[q][4 * k];
            const float* B = &Bs2[q][4 * k];
            nv.x = (xv.x - mu) * rstd * G[0] + B[0];
            nv.y = (xv.y - mu) * rstd * G[1] + B[1];
            nv.z = (xv.z - mu) * rstd * G[2] + B[2];
            nv.w = (xv.w - mu) * rstd * G[3] + B[3];
        }
        *(float4*)(&N[sIdx][q][4 * k]) = nv;
    }
    __syncthreads();

    float outv[2];
#pragma unroll
    for (int s = 0; s < 2; ++s) {
        float acc = bias;
#pragma unroll
        for (int u = 0; u < 5; ++u)
#pragma unroll
            for (int v = 0; v < 5; ++v)
                acc = fmaf(N[s][ti + u][tj + v + 2], wf[u * 5 + v], acc);
        outv[s] = fmaxf(acc, 0.0f);
        out3[(bg * 2 + s) * 4096 + p] = outv[s];
    }
#pragma unroll
    for (int s = 0; s < 2; ++s) {
        float v = outv[s], q = v * v;
#pragma unroll
        for (int o = 16; o; o >>= 1) {
            v += __shfl_down_sync(0xFFFFFFFFu, v, o);
            q += __shfl_down_sync(0xFFFFFFFFu, q, o);
        }
        if (lid == 0) { rs[wid][s] = v; rq[wid][s] = q; }
    }
    __syncthreads();
    if (tid < 2) {
        float s_ = 0.0f, q_ = 0.0f;
#pragma unroll
        for (int w = 0; w < 8; ++w) { s_ += rs[w][tid]; q_ += rq[w][tid]; }
        part3[(bg * 2 + tid) * 16 + tile] = make_float2(s_, q_);
    }
}

// ---------------------------------------------------------------------------
__device__ __forceinline__ float2 bstats(float s, float ss) {
    __shared__ float r0[32], r1[32];
    int tid = threadIdx.x, wid = tid >> 5, lid = tid & 31;
#pragma unroll
    for (int o = 16; o; o >>= 1) {
        s += __shfl_down_sync(0xFFFFFFFFu, s, o);
        ss += __shfl_down_sync(0xFFFFFFFFu, ss, o);
    }
    if (lid == 0) { r0[wid] = s; r1[wid] = ss; }
    __syncthreads();
    if (wid == 0) {
        s = r0[lid];
        ss = r1[lid];
#pragma unroll
        for (int o = 16; o; o >>= 1) {
            s += __shfl_down_sync(0xFFFFFFFFu, s, o);
            ss += __shfl_down_sync(0xFFFFFFFFu, ss, o);
        }
        if (lid == 0) { r0[0] = s; r1[0] = ss; }
    }
    __syncthreads();
    float2 res = make_float2(r0[0], r1[0]);
    __syncthreads();
    return res;
}

// ---------------------------------------------------------------------------
// tail: prologue = zero smem; wait; then layers 3..6. Grid 64, 1024 thr.
// ---------------------------------------------------------------------------
#define MT 1024
__global__ void __launch_bounds__(MT) tail_kernel(
    const float* __restrict__ in3, const float2* __restrict__ part3,
    const float* __restrict__ g3, const float* __restrict__ be3,
    const float* __restrict__ wp,
    const float* __restrict__ b4, const float* __restrict__ g4, const float* __restrict__ be4,
    const float* __restrict__ b5, const float* __restrict__ g5, const float* __restrict__ be5,
    const float* __restrict__ b6, const float* __restrict__ g6, const float* __restrict__ be6,
    float* __restrict__ hout) {
    __shared__ float SA[1156], SB[1156];
    __shared__ float2 st3;
    const int tid = threadIdx.x;
    const int b = blockIdx.x;

    for (int e = tid; e < 2312; e += MT) (e < 1156 ? SA : SB - 1156)[e] = 0.0f;

    GDC_WAIT();   // conv3k outputs ready

    if (tid < 32) {
        float2 a = (tid < 16) ? __ldg(&part3[b * 16 + tid]) : make_float2(0.f, 0.f);
        float sum = a.x, ssq = a.y;
#pragma unroll
        for (int o = 16; o; o >>= 1) {
            sum += __shfl_down_sync(0xFFFFFFFFu, sum, o);
            ssq += __shfl_down_sync(0xFFFFFFFFu, ssq, o);
        }
        if (tid == 0) {
            float mu = sum * (1.0f / 4096.0f);
            float var = ssq * (1.0f / 4096.0f) - mu * mu;
            st3 = make_float2(mu, rsqrtf(var + 1e-5f));
        }
    }
    __syncthreads();

    {
        float mu = st3.x, rstd = st3.y;
        const float* base = in3 + b * 4096;
        for (int e = tid; e < 512; e += MT) {
            int pr = e >> 4, g = e & 15;
            int r0 = 2 * pr, c = 4 * g;
            float4 x0 = *(const float4*)(base + r0 * 64 + c);
            float4 x1 = *(const float4*)(base + (r0 + 1) * 64 + c);
            float4 G0 = *(const float4*)(g3 + r0 * 64 + c);
            float4 G1 = *(const float4*)(g3 + (r0 + 1) * 64 + c);
            float4 B0 = *(const float4*)(be3 + r0 * 64 + c);
            float4 B1 = *(const float4*)(be3 + (r0 + 1) * 64 + c);
            float n00 = (x0.x - mu) * rstd * G0.x + B0.x;
            float n01 = (x0.y - mu) * rstd * G0.y + B0.y;
            float n10 = (x1.x - mu) * rstd * G1.x + B1.x;
            float n11 = (x1.y - mu) * rstd * G1.y + B1.y;
            SB[(pr + 1) * 34 + 2 * g + 1] = fmaxf(fmaxf(n00, n01), fmaxf(n10, n11));
            float m02 = (x0.z - mu) * rstd * G0.z + B0.z;
            float m03 = (x0.w - mu) * rstd * G0.w + B0.w;
            float m12 = (x1.z - mu) * rstd * G1.z + B1.z;
            float m13 = (x1.w - mu) * rstd * G1.w + B1.w;
            SB[(pr + 1) * 34 + 2 * g + 2] = fmaxf(fmaxf(m02, m03), fmaxf(m12, m13));
        }
    }
    __syncthreads();

    // conv4
    float s = 0.0f, ss = 0.0f;
    for (int e = tid; e < 1156; e += MT) {
        int i34 = e / 34, j34 = e - i34 * 34;
        if (i34 == 0 || i34 == 33 || j34 == 0 || j34 == 33) { SA[e] = 0.0f; continue; }
        int io = i34 - 1, jo = j34 - 1;
        int p = io * 32 + jo;
        float4 wq[3];
        const float4* wv4 = (const float4*)(wp + OFF_W4);
#pragma unroll
        for (int t = 0; t < 3; ++t) wq[t] = __ldg(wv4 + t * 1024 + p);
        const float* wf = (const float*)wq;
        const float* src = SB + io * 34 + jo;
        float acc = __ldg(b4 + p);
#pragma unroll
        for (int u = 0; u < 3; ++u)
#pragma unroll
            for (int v = 0; v < 3; ++v)
                acc = fmaf(src[u * 34 + v], wf[u * 3 + v], acc);
        acc = fmaxf(acc, 0.0f);
        SA[e] = acc;
        s += acc; ss += acc * acc;
    }
    float2 st = bstats(s, ss);
    float mu = st.x * (1.0f / 1024.0f);
    float rstd = rsqrtf(st.y * (1.0f / 1024.0f) - mu * mu + 1e-5f);
    for (int p = tid; p < 1024; p += MT) {
        int idx = ((p >> 5) + 1) * 34 + (p & 31) + 1;
        SA[idx] = (SA[idx] - mu) * rstd * __ldg(g4 + p) + __ldg(be4 + p);
    }
    __syncthreads();

    // conv5
    s = ss = 0.0f;
    for (int p = tid; p < 1024; p += MT) {
        int i = p >> 5, j = p & 31;
        float4 wq[3];
        const float4* wv5 = (const float4*)(wp + OFF_W5);
#pragma unroll
        for (int t = 0; t < 3; ++t) wq[t] = __ldg(wv5 + t * 1024 + p);
        const float* wf = (const float*)wq;
        const float* src = SA + i * 34 + j;
        float acc = __ldg(b5 + p);
#pragma unroll
        for (int u = 0; u < 3; ++u)
#pragma unroll
            for (int v = 0; v < 3; ++v)
                acc = fmaf(src[u * 34 + v], wf[u * 3 + v], acc);
        acc = fmaxf(acc, 0.0f);
        SB[(i + 1) * 34 + j + 1] = acc;
        s += acc; ss += acc * acc;
    }
    st = bstats(s, ss);
    mu = st.x * (1.0f / 1024.0f);
    rstd = rsqrtf(st.y * (1.0f / 1024.0f) - mu * mu + 1e-5f);
    for (int e = tid; e < 324; e += MT) {
        int i18 = e / 18, j18 = e - i18 * 18;
        if (i18 == 0 || i18 == 17 || j18 == 0 || j18 == 17) { SA[e] = 0.0f; continue; }
        int io = i18 - 1, jo = j18 - 1;
        float m = -CUDART_INF_F;
#pragma unroll
        for (int di = 0; di < 2; ++di)
#pragma unroll
            for (int dj = 0; dj < 2; ++dj) {
                int gi = 2 * io + di, gj = 2 * jo + dj;
                int q = gi * 32 + gj;
                float v = (SB[(gi + 1) * 34 + gj + 1] - mu) * rstd * __ldg(g5 + q) + __ldg(be5 + q);
                m = fmaxf(m, v);
            }
        SA[e] = m;
    }
    __syncthreads();

    // conv6
    s = ss = 0.0f;
    for (int p = tid; p < 256; p += MT) {
        int i = p >> 4, j = p & 15;
        float4 wq[3];
        const float4* wv6 = (const float4*)(wp + OFF_W6);
#pragma unroll
        for (int t = 0; t < 3; ++t) wq[t] = __ldg(wv6 + t * 256 + p);
        const float* wf = (const float*)wq;
        const float* src = SA + i * 18 + j;
        float acc = __ldg(b6 + p);
#pragma unroll
        for (int u = 0; u < 3; ++u)
#pragma unroll
            for (int v = 0; v < 3; ++v)
                acc = fmaf(src[u * 18 + v], wf[u * 3 + v], acc);
        acc = fmaxf(acc, 0.0f);
        SB[p] = acc;
        s += acc; ss += acc * acc;
    }
    st = bstats(s, ss);
    mu = st.x * (1.0f / 256.0f);
    rstd = rsqrtf(st.y * (1.0f / 256.0f) - mu * mu + 1e-5f);
    for (int p = tid; p < 256; p += MT)
        hout[b * 256 + p] = (SB[p] - mu) * rstd * __ldg(g6 + p) + __ldg(be6 + p);
}

// ---------------------------------------------------------------------------
// FC: prologue = all fcw fragments + bias; wait; then h. Grid (32,16), 256.
// ---------------------------------------------------------------------------
__global__ void __launch_bounds__(256) fc_kernel(const float* __restrict__ h,
                                                 const float* __restrict__ fcw,
                                                 const float* __restrict__ fcb,
                                                 float* __restrict__ logits) {
    __shared__ float hs[4 * 256];
    const int ct = blockIdx.x, rg = blockIdx.y;
    const int tid = threadIdx.x, wid = tid >> 5, lid = tid & 31;

    // prologue: weight fragments for all 4 outputs (host inputs)
    const int obase = ct * 32 + wid * 4;
    float4 wa[4], wb[4];
    float bo[4];
#pragma unroll
    for (int t = 0; t < 4; ++t) {
        const float4* wr = (const float4*)(fcw + (obase + t) * 256 + lid * 8);
        wa[t] = __ldg(wr);
        wb[t] = __ldg(wr + 1);
        bo[t] = __ldg(fcb + obase + t);
    }

    GDC_WAIT();   // tail output h ready

    for (int e = tid; e < 1024; e += 256) hs[e] = h[rg * 1024 + e];
    __syncthreads();

    float hr[4][8];
#pragma unroll
    for (int r = 0; r < 4; ++r)
#pragma unroll
        for (int c = 0; c < 8; ++c) hr[r][c] = hs[r * 256 + lid * 8 + c];

#pragma unroll
    for (int t = 0; t < 4; ++t) {
        float a[4];
#pragma unroll
        for (int r = 0; r < 4; ++r) {
            a[r] = hr[r][0] * wa[t].x + hr[r][1] * wa[t].y + hr[r][2] * wa[t].z + hr[r][3] * wa[t].w
                 + hr[r][4] * wb[t].x + hr[r][5] * wb[t].y + hr[r][6] * wb[t].z + hr[r][7] * wb[t].w;
        }
#pragma unroll
        for (int r = 0; r < 4; ++r)
#pragma unroll
            for (int off = 16; off; off >>= 1) a[r] += __shfl_down_sync(0xFFFFFFFFu, a[r], off);
        if (lid == 0) {
#pragma unroll
            for (int r = 0; r < 4; ++r) logits[(rg * 4 + r) * 1024 + obase + t] = a[r] + bo[t];
        }
    }
}

// ---------------------------------------------------------------------------
// Softmax: grid=64, 512 threads.
// ---------------------------------------------------------------------------
__global__ void __launch_bounds__(512) softmax_kernel(const float* __restrict__ logits,
                                                      float* __restrict__ out) {
    __shared__ float red[16];
    const int b = blockIdx.x, tid = threadIdx.x, wid = tid >> 5, lid = tid & 31;

    GDC_WAIT();   // fc logits ready

    const float* row = logits + b * 1024;
    float v0 = row[tid], v1 = row[512 + tid];
    float mx = fmaxf(v0, v1);
#pragma unroll
    for (int o = 16; o; o >>= 1) mx = fmaxf(mx, __shfl_xor_sync(0xFFFFFFFFu, mx, o));
    if (lid == 0) red[wid] = mx;
    __syncthreads();
    mx = red[0];
#pragma unroll
    for (int w = 1; w < 16; ++w) mx = fmaxf(mx, red[w]);
    __syncthreads();

    float e0 = __expf(v0 - mx), e1 = __expf(v1 - mx);
    float ps = e0 + e1;
#pragma unroll
    for (int o = 16; o; o >>= 1) ps += __shfl_xor_sync(0xFFFFFFFFu, ps, o);
    if (lid == 0) red[wid] = ps;
    __syncthreads();
    float tot = 0.0f;
#pragma unroll
    for (int w = 0; w < 16; ++w) tot += red[w];
    float inv = 1.0f / tot;
    out[b * 1024 + tid] = e0 * inv;
    out[b * 1024 + 512 + tid] = e1 * inv;
}

// ---------------------------------------------------------------------------
template <typename K, typename... Args>
static inline void launch_pdl(K kernel, dim3 grid, dim3 block, Args... args) {
    cudaLaunchConfig_t cfg = {};
    cfg.gridDim = grid;
    cfg.blockDim = block;
    cudaLaunchAttribute at[1];
    at[0].id = cudaLaunchAttributeProgrammaticStreamSerialization;
    at[0].val.programmaticStreamSerializationAllowed = 1;
    cfg.attrs = at;
    cfg.numAttrs = 1;
    cudaLaunchKernelEx(&cfg, kernel, args...);
}

extern "C" void kernel_launch(void* const* d_in, const int* in_sizes, int n_in,
                              void* d_out, int out_size) {
    (void)in_sizes; (void)n_in; (void)out_size;

    const float* x = (const float*)d_in[0];
    const float* w[7];
    const float* bi[7];
    const float* gg[7];
    const float* bb[7];
    for (int L = 1; L <= 6; ++L) {
        w[L]  = (const float*)d_in[1 + 4 * (L - 1) + 0];
        bi[L] = (const float*)d_in[1 + 4 * (L - 1) + 1];
        gg[L] = (const float*)d_in[1 + 4 * (L - 1) + 2];
        bb[L] = (const float*)d_in[1 + 4 * (L - 1) + 3];
    }
    const float* fcw = (const float*)d_in[25];
    const float* fcb = (const float*)d_in[26];
    float* out = (float*)d_out;

    float *c1, *o2, *o3, *h, *lg, *wp;
    float2 *p1, *p2, *p3;
    cudaGetSymbolAddress((void**)&c1, g_conv1);
    cudaGetSymbolAddress((void**)&o2, g_out2);
    cudaGetSymbolAddress((void**)&o3, g_out3);
    cudaGetSymbolAddress((void**)&h, g_h);
    cudaGetSymbolAddress((void**)&lg, g_logits);
    cudaGetSymbolAddress((void**)&wp, g_wpack);
    cudaGetSymbolAddress((void**)&p1, g_part1);
    cudaGetSymbolAddress((void**)&p2, g_part2);
    cudaGetSymbolAddress((void**)&p3, g_part3);

    repack_kernel<<<256, 256>>>(w[1], w[2], w[3], w[4], w[5], w[6], wp);
    launch_pdl(conv1_kernel, dim3(64, 8), dim3(256),
               x, wp, (const float*)bi[1], c1, p1);
    launch_pdl(conv2k_kernel, dim3(16, 16), dim3(256),
               (const float*)c1, (const float2*)p1, gg[1], bb[1],
               (const float*)wp, bi[2], o2, p2);
    launch_pdl(conv3k_kernel, dim3(16, 32), dim3(256),
               (const float*)o2, (const float2*)p2, gg[2], bb[2],
               (const float*)wp, bi[3], o3, p3);
    launch_pdl(tail_kernel, dim3(64), dim3(MT),
               (const float*)o3, (const float2*)p3, gg[3], bb[3],
               (const float*)wp,
               bi[4], gg[4], bb[4],
               bi[5], gg[5], bb[5],
               bi[6], gg[6], bb[6],
               h);
    launch_pdl(fc_kernel, dim3(32, 16), dim3(256),
               (const float*)h, fcw, fcb, lg);
    launch_pdl(softmax_kernel, dim3(64), dim3(512),
               (const float*)lg, out);
}